// round 9
// baseline (speedup 1.0000x reference)
#include <cuda_runtime.h>

// LQE_17841294147886 — fused softmax/top4/MLP/broadcast-add
// R8: warp-per-side softmax with aligned 36-float window (9x LDS.128 +
//     uniform -inf masking) and sort-network top-4 (sort4+bitonic merge,
//     186 minmax vs 231). MLP/staging/out identical to R6 (98.3us).

#define TPB        128
#define NBINS      33
#define DPOS       132
#define TILE_POS   32
#define NTILES     4
#define BUF_FLOATS (TILE_POS * DPOS)      // 4224
#define STAT_ROW   20
#define WROW       20
#define NCOUT      80
#define LOG2E      1.4426950408889634f

typedef unsigned long long u64;

__device__ __forceinline__ u64 fma2(u64 a, u64 b, u64 c) {
    u64 d; asm("fma.rn.f32x2 %0, %1, %2, %3;" : "=l"(d) : "l"(a), "l"(b), "l"(c));
    return d;
}
__device__ __forceinline__ u64 addf2(u64 a, u64 b) {
    u64 d; asm("add.rn.f32x2 %0, %1, %2;" : "=l"(d) : "l"(a), "l"(b));
    return d;
}
__device__ __forceinline__ void unpack2(u64 v, float& lo, float& hi) {
    asm("mov.b64 {%0, %1}, %2;" : "=f"(lo), "=f"(hi) : "l"(v));
}
__device__ __forceinline__ float ex2f(float x) {
    float r; asm("ex2.approx.f32 %0, %1;" : "=f"(r) : "f"(x));
    return r;
}
__device__ __forceinline__ float rcpf(float x) {
    float r; asm("rcp.approx.f32 %0, %1;" : "=f"(r) : "f"(x));
    return r;
}

// sort 4 floats descending: 10 ops
__device__ __forceinline__ void sort4(float x0, float x1, float x2, float x3,
                                      float& a, float& b, float& c, float& d) {
    float p = fmaxf(x0, x1), q = fminf(x0, x1);
    float r = fmaxf(x2, x3), s = fminf(x2, x3);
    a = fmaxf(p, r); float tt = fminf(p, r);
    d = fminf(q, s); float u  = fmaxf(q, s);
    b = fmaxf(tt, u); c = fminf(tt, u);
}

// merge sorted-desc R with sorted-desc A -> top4 desc in R: 12 ops
__device__ __forceinline__ void merge4(float& r0, float& r1, float& r2, float& r3,
                                       float a0, float a1, float a2, float a3) {
    float L0 = fmaxf(r0, a3), L1 = fmaxf(r1, a2);
    float L2 = fmaxf(r2, a1), L3 = fmaxf(r3, a0);
    float m0 = fmaxf(L0, L2), m2 = fminf(L0, L2);
    float m1 = fmaxf(L1, L3), m3 = fminf(L1, L3);
    r0 = fmaxf(m0, m1); r1 = fminf(m0, m1);
    r2 = fmaxf(m2, m3); r3 = fminf(m2, m3);
}

__global__ __launch_bounds__(TPB, 8)
void lqe_kernel(const float* __restrict__ scores,
                const float* __restrict__ pred,
                const float* __restrict__ w1,
                const float* __restrict__ b1,
                const float* __restrict__ w2,
                const float* __restrict__ b2,
                float* __restrict__ out)
{
    extern __shared__ float smem[];
    float* buf  = smem;                              // [32][132] raw tile copy
    float* stat = smem + BUF_FLOATS;                 // [32][20] packed stats
    float* wsm  = stat + TILE_POS * STAT_ROW;        // [64][20] folded weights
    float* qs   = wsm + 64 * WROW;                   // [128]

    const int t  = threadIdx.x;
    const int w  = t >> 5;        // softmax: side (warp-uniform)
    const int pL = t & 31;        // softmax: position
    const int c  = t & 3;         // MLP: j-chunk
    const int p  = t >> 2;        // MLP: position
    const int blockStart = blockIdx.x * TPB;
    const float b2v = __ldg(b2);
    const float NI  = __int_as_float(0xff800000);   // -inf

    // ---- folded weight table: wsm[j][k] ----
    // k<16: w_eff[j][4s+i] = w1[j][5s+i] + 0.25*w1[j][5s+4]; k16=b1[j]; k17=w2[j]
    #pragma unroll
    for (int k = 0; k < (64 * WROW) / TPB; k++) {
        int f   = t + k * TPB;
        int row = f / WROW;
        int cc  = f - row * WROW;
        float v = 0.f;
        if (cc < 16) {
            int ss = cc >> 2, ii = cc & 3;
            v = __ldg(w1 + row * 20 + 5 * ss + ii)
              + 0.25f * __ldg(w1 + row * 20 + 5 * ss + 4);
        } else if (cc == 16) v = __ldg(b1 + row);
        else if (cc == 17)   v = __ldg(w2 + row);
        wsm[f] = v;
    }

    const float4* g4 = (const float4*)(pred + (size_t)blockStart * DPOS);
    float4* b4 = (float4*)buf;

    // aligned window base for this thread's (pos, side) row:
    // row floats [B, B+33), B = pL*132 + 33w, B mod 4 == w.
    const float4* win = (const float4*)(buf + pL * DPOS + NBINS * w - w);

    #pragma unroll 1
    for (int tau = 0; tau < NTILES; tau++) {
        // ---- stage tile: pure linear float4 copy (1056 f4 = 8*128 + 32) ----
        const float4* gt = g4 + tau * (TILE_POS * NBINS);
        #pragma unroll
        for (int j = 0; j < 8; j++)
            b4[t + j * TPB] = gt[t + j * TPB];
        if (t < 32) b4[t + 8 * TPB] = gt[t + 8 * TPB];
        __syncthreads();

        // ---- softmax denom + top4: 9 aligned f4 + uniform mask + sort nets ----
        {
            float r0, r1, r2, r3;          // running top-4 (desc)
            float sum0 = 0.f, sum1 = 0.f;
            {
                float4 q0 = win[0];        // head: first w floats invalid
                if (w > 0) q0.x = NI;
                if (w > 1) q0.y = NI;
                if (w > 2) q0.z = NI;
                float e0 = ex2f(q0.x * LOG2E);
                float e1 = ex2f(q0.y * LOG2E);
                float e2 = ex2f(q0.z * LOG2E);
                float e3 = ex2f(q0.w * LOG2E);
                sum0 = e0 + e2; sum1 = e1 + e3;
                sort4(e0, e1, e2, e3, r0, r1, r2, r3);
            }
            #pragma unroll
            for (int g = 1; g < 8; g++) {
                float4 v = win[g];
                float e0 = ex2f(v.x * LOG2E);
                float e1 = ex2f(v.y * LOG2E);
                float e2 = ex2f(v.z * LOG2E);
                float e3 = ex2f(v.w * LOG2E);
                sum0 += e0 + e2; sum1 += e1 + e3;
                float a0, a1, a2, a3;
                sort4(e0, e1, e2, e3, a0, a1, a2, a3);
                merge4(r0, r1, r2, r3, a0, a1, a2, a3);
            }
            {
                float4 q8 = win[8];        // tail: last (3-w) floats invalid
                if (w < 3) q8.w = NI;
                if (w < 2) q8.z = NI;
                if (w < 1) q8.y = NI;
                float e0 = ex2f(q8.x * LOG2E);
                float e1 = ex2f(q8.y * LOG2E);
                float e2 = ex2f(q8.z * LOG2E);
                float e3 = ex2f(q8.w * LOG2E);
                sum0 += e0 + e2; sum1 += e1 + e3;
                float a0, a1, a2, a3;
                sort4(e0, e1, e2, e3, a0, a1, a2, a3);
                merge4(r0, r1, r2, r3, a0, a1, a2, a3);
            }
            float inv = rcpf(sum0 + sum1);
            *(float4*)(stat + pL * STAT_ROW + 4 * w) =
                make_float4(r0 * inv, r1 * inv, r2 * inv, r3 * inv);
        }
        __syncthreads();   // stats cross warps now

        // ---- per-tile MLP: quad per position, 16 units/thread (as R6) ----
        {
            const ulonglong2* srow = (const ulonglong2*)(stat + p * STAT_ROW);
            ulonglong2 sA = srow[0];
            ulonglong2 sB = srow[1];
            ulonglong2 sC = srow[2];
            ulonglong2 sD = srow[3];
            float q = 0.f;
            #pragma unroll 4
            for (int i = 0; i < 16; i++) {
                int j = 4 * i + c;     // same row across quads -> broadcast LDS
                const ulonglong2* wrow = (const ulonglong2*)(wsm + j * WROW);
                ulonglong2 wa = wrow[0];
                ulonglong2 wb = wrow[1];
                ulonglong2 wc2 = wrow[2];
                ulonglong2 wd = wrow[3];
                float2 bw = *(const float2*)(wsm + j * WROW + 16);

                u64 accA = fma2(wa.x, sA.x, 0ull);
                u64 accB = fma2(wc2.x, sC.x, 0ull);
                accA = fma2(wa.y, sA.y, accA);
                accB = fma2(wc2.y, sC.y, accB);
                accA = fma2(wb.x, sB.x, accA);
                accB = fma2(wd.x, sD.x, accB);
                accA = fma2(wb.y, sB.y, accA);
                accB = fma2(wd.y, sD.y, accB);

                u64 accS = addf2(accA, accB);
                float d0, d1; unpack2(accS, d0, d1);
                float h = (d0 + d1) + bw.x;
                h = fmaxf(h, 0.f);
                q = fmaf(h, bw.y, q);
            }
            q += __shfl_xor_sync(0xffffffffu, q, 1);
            q += __shfl_xor_sync(0xffffffffu, q, 2);
            if (c == 0) qs[tau * TILE_POS + p] = q + b2v;
        }
        __syncthreads();   // buf & stat reuse next tile; qs for out phase
    }

    // ---- broadcast-add into 80 scores/pos, float4-coalesced ----
    {
        const float4* sp = (const float4*)scores + (size_t)blockStart * (NCOUT / 4) + t;
        float4*       op = (float4*)out          + (size_t)blockStart * (NCOUT / 4) + t;
        int pp = t / (NCOUT / 4);
        int r  = t - pp * (NCOUT / 4);
        #pragma unroll 4
        for (int j = 0; j < NCOUT / 4; j++) {
            float qv = qs[pp];
            float4 v = *sp;
            v.x += qv; v.y += qv; v.z += qv; v.w += qv;
            *op = v;
            sp += TPB; op += TPB;
            r += 8; pp += 6;                 // 128 = 6*20 + 8
            if (r >= 20) { r -= 20; pp += 1; }
        }
    }
}

extern "C" void kernel_launch(void* const* d_in, const int* in_sizes, int n_in,
                              void* d_out, int out_size)
{
    const float* scores = (const float*)d_in[0];
    const float* pred   = (const float*)d_in[1];
    const float* w1     = (const float*)d_in[2];
    const float* b1     = (const float*)d_in[3];
    const float* w2     = (const float*)d_in[4];
    const float* b2     = (const float*)d_in[5];
    // d_in[6] = k_top (fixed 4, compile-time specialized)

    int npos = in_sizes[1] / DPOS;     // 320000
    int grid = npos / TPB;             // 2500 exact

    size_t smem = (size_t)(BUF_FLOATS + TILE_POS * STAT_ROW + 64 * WROW + TPB)
                  * sizeof(float);
    lqe_kernel<<<grid, TPB, smem>>>(scores, pred, w1, b1, w2, b2, (float*)d_out);
}

// round 10
// speedup vs baseline: 1.1179x; 1.1179x over previous
#include <cuda_runtime.h>
#include <cstdint>

// LQE_17841294147886 — fused softmax/top4/MLP/broadcast-add
// R9: cp.async software pipeline. Tile τ+1 staged via LDGSTS during tile τ's
//     MLP/out (single buffer, hazard-free by barrier placement); scores
//     prefetched per tile into regs; out-add moved inside the tile loop.
//     Softmax (sort-network) and MLP identical to R8.

#define TPB        128
#define NBINS      33
#define DPOS       132
#define TILE_POS   32
#define NTILES     4
#define BUF_FLOATS (TILE_POS * DPOS)      // 4224
#define STAT_ROW   20
#define WROW       20
#define NCOUT      80
#define LOG2E      1.4426950408889634f

typedef unsigned long long u64;

__device__ __forceinline__ u64 fma2(u64 a, u64 b, u64 c) {
    u64 d; asm("fma.rn.f32x2 %0, %1, %2, %3;" : "=l"(d) : "l"(a), "l"(b), "l"(c));
    return d;
}
__device__ __forceinline__ u64 addf2(u64 a, u64 b) {
    u64 d; asm("add.rn.f32x2 %0, %1, %2;" : "=l"(d) : "l"(a), "l"(b));
    return d;
}
__device__ __forceinline__ void unpack2(u64 v, float& lo, float& hi) {
    asm("mov.b64 {%0, %1}, %2;" : "=f"(lo), "=f"(hi) : "l"(v));
}
__device__ __forceinline__ float ex2f(float x) {
    float r; asm("ex2.approx.f32 %0, %1;" : "=f"(r) : "f"(x));
    return r;
}
__device__ __forceinline__ float rcpf(float x) {
    float r; asm("rcp.approx.f32 %0, %1;" : "=f"(r) : "f"(x));
    return r;
}
__device__ __forceinline__ void cp16(uint32_t dst, const void* src) {
    asm volatile("cp.async.cg.shared.global [%0], [%1], 16;"
                 :: "r"(dst), "l"(src));
}
#define CP_COMMIT() asm volatile("cp.async.commit_group;" ::: "memory")
#define CP_WAIT0()  asm volatile("cp.async.wait_group 0;" ::: "memory")

// sort 4 floats descending: 10 ops
__device__ __forceinline__ void sort4(float x0, float x1, float x2, float x3,
                                      float& a, float& b, float& c, float& d) {
    float p = fmaxf(x0, x1), q = fminf(x0, x1);
    float r = fmaxf(x2, x3), s = fminf(x2, x3);
    a = fmaxf(p, r); float tt = fminf(p, r);
    d = fminf(q, s); float u  = fmaxf(q, s);
    b = fmaxf(tt, u); c = fminf(tt, u);
}
// merge sorted-desc R with sorted-desc A -> top4 desc in R: 12 ops
__device__ __forceinline__ void merge4(float& r0, float& r1, float& r2, float& r3,
                                       float a0, float a1, float a2, float a3) {
    float L0 = fmaxf(r0, a3), L1 = fmaxf(r1, a2);
    float L2 = fmaxf(r2, a1), L3 = fmaxf(r3, a0);
    float m0 = fmaxf(L0, L2), m2 = fminf(L0, L2);
    float m1 = fmaxf(L1, L3), m3 = fminf(L1, L3);
    r0 = fmaxf(m0, m1); r1 = fminf(m0, m1);
    r2 = fmaxf(m2, m3); r3 = fminf(m2, m3);
}

__global__ __launch_bounds__(TPB, 8)
void lqe_kernel(const float* __restrict__ scores,
                const float* __restrict__ pred,
                const float* __restrict__ w1,
                const float* __restrict__ b1,
                const float* __restrict__ w2,
                const float* __restrict__ b2,
                float* __restrict__ out)
{
    extern __shared__ float smem[];
    float* buf  = smem;                              // [32][132] tile (single buf)
    float* stat = smem + BUF_FLOATS;                 // [32][20] packed stats
    float* wsm  = stat + TILE_POS * STAT_ROW;        // [64][20] folded weights
    float* qs   = wsm + 64 * WROW;                   // [128]

    const int t  = threadIdx.x;
    const int w  = t >> 5;        // softmax: side (warp-uniform)
    const int pL = t & 31;        // softmax: position
    const int c  = t & 3;         // MLP: j-chunk
    const int p  = t >> 2;        // MLP: position
    const int blockStart = blockIdx.x * TPB;
    const float b2v = __ldg(b2);
    const float NI  = __int_as_float(0xff800000);   // -inf

    const uint32_t bufu = (uint32_t)__cvta_generic_to_shared(buf);
    const float4* g4 = (const float4*)(pred + (size_t)blockStart * DPOS);

    // ---- kick off tile 0 staging immediately (overlaps weight-table build) ----
    {
        const float4* gt = g4;
        #pragma unroll
        for (int j = 0; j < 8; j++)
            cp16(bufu + (uint32_t)(t + j * TPB) * 16u, gt + t + j * TPB);
        if (t < 32)
            cp16(bufu + (uint32_t)(t + 8 * TPB) * 16u, gt + t + 8 * TPB);
        CP_COMMIT();
    }

    // ---- folded weight table: wsm[j][k] ----
    // k<16: w_eff[j][4s+i] = w1[j][5s+i] + 0.25*w1[j][5s+4]; k16=b1[j]; k17=w2[j]
    #pragma unroll
    for (int k = 0; k < (64 * WROW) / TPB; k++) {
        int f   = t + k * TPB;
        int row = f / WROW;
        int cc  = f - row * WROW;
        float v = 0.f;
        if (cc < 16) {
            int ss = cc >> 2, ii = cc & 3;
            v = __ldg(w1 + row * 20 + 5 * ss + ii)
              + 0.25f * __ldg(w1 + row * 20 + 5 * ss + 4);
        } else if (cc == 16) v = __ldg(b1 + row);
        else if (cc == 17)   v = __ldg(w2 + row);
        wsm[f] = v;
    }

    // aligned window base: row floats [B, B+33), B = pL*132 + 33w, B mod 4 == w
    const float4* win = (const float4*)(buf + pL * DPOS + NBINS * w - w);
    const float4* sc4 = (const float4*)scores + (size_t)blockStart * (NCOUT / 4);
    float4*       ou4 = (float4*)out          + (size_t)blockStart * (NCOUT / 4);
    const int posA = t / (NCOUT / 4);          // out-phase base pos / remainder
    const int remA = t - posA * (NCOUT / 4);

    #pragma unroll
    for (int tau = 0; tau < NTILES; tau++) {
        CP_WAIT0();
        __syncthreads();                       // buf(tau) visible to all

        // ---- prefetch this tile's scores (consumed after 2 barriers) ----
        float4 rs0 = sc4[tau * 640 + t];
        float4 rs1 = sc4[tau * 640 + t + 128];
        float4 rs2 = sc4[tau * 640 + t + 256];
        float4 rs3 = sc4[tau * 640 + t + 384];
        float4 rs4 = sc4[tau * 640 + t + 512];

        // ---- softmax denom + top4: 9 aligned f4 + uniform mask + sort nets ----
        {
            float r0, r1, r2, r3;
            float sum0, sum1;
            {
                float4 q0 = win[0];            // head: first w floats invalid
                if (w > 0) q0.x = NI;
                if (w > 1) q0.y = NI;
                if (w > 2) q0.z = NI;
                float e0 = ex2f(q0.x * LOG2E);
                float e1 = ex2f(q0.y * LOG2E);
                float e2 = ex2f(q0.z * LOG2E);
                float e3 = ex2f(q0.w * LOG2E);
                sum0 = e0 + e2; sum1 = e1 + e3;
                sort4(e0, e1, e2, e3, r0, r1, r2, r3);
            }
            #pragma unroll
            for (int g = 1; g < 8; g++) {
                float4 v = win[g];
                float e0 = ex2f(v.x * LOG2E);
                float e1 = ex2f(v.y * LOG2E);
                float e2 = ex2f(v.z * LOG2E);
                float e3 = ex2f(v.w * LOG2E);
                sum0 += e0 + e2; sum1 += e1 + e3;
                float a0, a1, a2, a3;
                sort4(e0, e1, e2, e3, a0, a1, a2, a3);
                merge4(r0, r1, r2, r3, a0, a1, a2, a3);
            }
            {
                float4 q8 = win[8];            // tail: last (3-w) floats invalid
                if (w < 3) q8.w = NI;
                if (w < 2) q8.z = NI;
                if (w < 1) q8.y = NI;
                float e0 = ex2f(q8.x * LOG2E);
                float e1 = ex2f(q8.y * LOG2E);
                float e2 = ex2f(q8.z * LOG2E);
                float e3 = ex2f(q8.w * LOG2E);
                sum0 += e0 + e2; sum1 += e1 + e3;
                float a0, a1, a2, a3;
                sort4(e0, e1, e2, e3, a0, a1, a2, a3);
                merge4(r0, r1, r2, r3, a0, a1, a2, a3);
            }
            float inv = rcpf(sum0 + sum1);
            *(float4*)(stat + pL * STAT_ROW + 4 * w) =
                make_float4(r0 * inv, r1 * inv, r2 * inv, r3 * inv);
        }
        __syncthreads();                       // stat ready; all buf reads done

        // ---- stage NEXT tile into buf via cp.async (in flight thru MLP/out) ----
        if (tau < NTILES - 1) {
            const float4* gt = g4 + (tau + 1) * (TILE_POS * NBINS);
            #pragma unroll
            for (int j = 0; j < 8; j++)
                cp16(bufu + (uint32_t)(t + j * TPB) * 16u, gt + t + j * TPB);
            if (t < 32)
                cp16(bufu + (uint32_t)(t + 8 * TPB) * 16u, gt + t + 8 * TPB);
            CP_COMMIT();
        }

        // ---- per-tile MLP: quad per position, 16 units/thread ----
        {
            const ulonglong2* srow = (const ulonglong2*)(stat + p * STAT_ROW);
            ulonglong2 sA = srow[0];
            ulonglong2 sB = srow[1];
            ulonglong2 sC = srow[2];
            ulonglong2 sD = srow[3];
            float q = 0.f;
            #pragma unroll 4
            for (int i = 0; i < 16; i++) {
                int j = 4 * i + c;             // broadcast LDS across quads
                const ulonglong2* wrow = (const ulonglong2*)(wsm + j * WROW);
                ulonglong2 wa = wrow[0];
                ulonglong2 wb = wrow[1];
                ulonglong2 wc2 = wrow[2];
                ulonglong2 wd = wrow[3];
                float2 bw = *(const float2*)(wsm + j * WROW + 16);

                u64 accA = fma2(wa.x, sA.x, 0ull);
                u64 accB = fma2(wc2.x, sC.x, 0ull);
                accA = fma2(wa.y, sA.y, accA);
                accB = fma2(wc2.y, sC.y, accB);
                accA = fma2(wb.x, sB.x, accA);
                accB = fma2(wd.x, sD.x, accB);
                accA = fma2(wb.y, sB.y, accA);
                accB = fma2(wd.y, sD.y, accB);

                u64 accS = addf2(accA, accB);
                float d0, d1; unpack2(accS, d0, d1);
                float h = (d0 + d1) + bw.x;
                h = fmaxf(h, 0.f);
                q = fmaf(h, bw.y, q);
            }
            q += __shfl_xor_sync(0xffffffffu, q, 1);
            q += __shfl_xor_sync(0xffffffffu, q, 2);
            if (c == 0) qs[tau * TILE_POS + p] = q + b2v;
        }
        __syncthreads();                       // qs(tau) visible

        // ---- out-add for this tile's 32 positions (scores already in regs) ----
        {
            const float* qb = qs + tau * TILE_POS;
            int pp = posA, r = remA;
            float4 v;
            float qv;
            qv = qb[pp]; v = rs0;
            v.x += qv; v.y += qv; v.z += qv; v.w += qv;
            ou4[tau * 640 + t] = v;
            r += 8; pp += 6; if (r >= 20) { r -= 20; pp += 1; }
            qv = qb[pp]; v = rs1;
            v.x += qv; v.y += qv; v.z += qv; v.w += qv;
            ou4[tau * 640 + t + 128] = v;
            r += 8; pp += 6; if (r >= 20) { r -= 20; pp += 1; }
            qv = qb[pp]; v = rs2;
            v.x += qv; v.y += qv; v.z += qv; v.w += qv;
            ou4[tau * 640 + t + 256] = v;
            r += 8; pp += 6; if (r >= 20) { r -= 20; pp += 1; }
            qv = qb[pp]; v = rs3;
            v.x += qv; v.y += qv; v.z += qv; v.w += qv;
            ou4[tau * 640 + t + 384] = v;
            r += 8; pp += 6; if (r >= 20) { r -= 20; pp += 1; }
            qv = qb[pp]; v = rs4;
            v.x += qv; v.y += qv; v.z += qv; v.w += qv;
            ou4[tau * 640 + t + 512] = v;
        }
    }
}

extern "C" void kernel_launch(void* const* d_in, const int* in_sizes, int n_in,
                              void* d_out, int out_size)
{
    const float* scores = (const float*)d_in[0];
    const float* pred   = (const float*)d_in[1];
    const float* w1     = (const float*)d_in[2];
    const float* b1     = (const float*)d_in[3];
    const float* w2     = (const float*)d_in[4];
    const float* b2     = (const float*)d_in[5];
    // d_in[6] = k_top (fixed 4, compile-time specialized)

    int npos = in_sizes[1] / DPOS;     // 320000
    int grid = npos / TPB;             // 2500 exact

    size_t smem = (size_t)(BUF_FLOATS + TILE_POS * STAT_ROW + 64 * WROW + TPB)
                  * sizeof(float);
    lqe_kernel<<<grid, TPB, smem>>>(scores, pred, w1, b1, w2, b2, (float*)d_out);
}

// round 11
// speedup vs baseline: 1.1960x; 1.0699x over previous
#include <cuda_runtime.h>
#include <cstdint>

// LQE_17841294147886 — fused softmax/top4/MLP/broadcast-add
// R10: TRUE double buffer. copy(τ+1) issued at tile top (window = full tile
//      compute vs R9's MLP+out only). 42KB smem -> 5 blocks/SM (accepted:
//      kernel is not occupancy-bound, R4 evidence). Compute = R8/R9.

#define TPB        128
#define NBINS      33
#define DPOS       132
#define TILE_POS   32
#define NTILES     4
#define BUF_FLOATS (TILE_POS * DPOS)      // 4224 per buffer
#define STAT_ROW   20
#define WROW       20
#define NCOUT      80
#define LOG2E      1.4426950408889634f

typedef unsigned long long u64;

__device__ __forceinline__ u64 fma2(u64 a, u64 b, u64 c) {
    u64 d; asm("fma.rn.f32x2 %0, %1, %2, %3;" : "=l"(d) : "l"(a), "l"(b), "l"(c));
    return d;
}
__device__ __forceinline__ u64 addf2(u64 a, u64 b) {
    u64 d; asm("add.rn.f32x2 %0, %1, %2;" : "=l"(d) : "l"(a), "l"(b));
    return d;
}
__device__ __forceinline__ void unpack2(u64 v, float& lo, float& hi) {
    asm("mov.b64 {%0, %1}, %2;" : "=f"(lo), "=f"(hi) : "l"(v));
}
__device__ __forceinline__ float ex2f(float x) {
    float r; asm("ex2.approx.f32 %0, %1;" : "=f"(r) : "f"(x));
    return r;
}
__device__ __forceinline__ float rcpf(float x) {
    float r; asm("rcp.approx.f32 %0, %1;" : "=f"(r) : "f"(x));
    return r;
}
__device__ __forceinline__ void cp16(uint32_t dst, const void* src) {
    asm volatile("cp.async.cg.shared.global [%0], [%1], 16;"
                 :: "r"(dst), "l"(src));
}
#define CP_COMMIT() asm volatile("cp.async.commit_group;" ::: "memory")
#define CP_WAIT0()  asm volatile("cp.async.wait_group 0;" ::: "memory")

// sort 4 floats descending: 10 ops
__device__ __forceinline__ void sort4(float x0, float x1, float x2, float x3,
                                      float& a, float& b, float& c, float& d) {
    float p = fmaxf(x0, x1), q = fminf(x0, x1);
    float r = fmaxf(x2, x3), s = fminf(x2, x3);
    a = fmaxf(p, r); float tt = fminf(p, r);
    d = fminf(q, s); float u  = fmaxf(q, s);
    b = fmaxf(tt, u); c = fminf(tt, u);
}
// merge sorted-desc R with sorted-desc A -> top4 desc in R: 12 ops
__device__ __forceinline__ void merge4(float& r0, float& r1, float& r2, float& r3,
                                       float a0, float a1, float a2, float a3) {
    float L0 = fmaxf(r0, a3), L1 = fmaxf(r1, a2);
    float L2 = fmaxf(r2, a1), L3 = fmaxf(r3, a0);
    float m0 = fmaxf(L0, L2), m2 = fminf(L0, L2);
    float m1 = fmaxf(L1, L3), m3 = fminf(L1, L3);
    r0 = fmaxf(m0, m1); r1 = fminf(m0, m1);
    r2 = fmaxf(m2, m3); r3 = fminf(m2, m3);
}

__global__ __launch_bounds__(TPB, 5)
void lqe_kernel(const float* __restrict__ scores,
                const float* __restrict__ pred,
                const float* __restrict__ w1,
                const float* __restrict__ b1,
                const float* __restrict__ w2,
                const float* __restrict__ b2,
                float* __restrict__ out)
{
    extern __shared__ float smem[];
    float* buf0 = smem;                               // [32][132] tile buffer A
    float* buf1 = smem + BUF_FLOATS;                  // [32][132] tile buffer B
    float* stat = smem + 2 * BUF_FLOATS;              // [32][20] packed stats
    float* wsm  = stat + TILE_POS * STAT_ROW;         // [64][20] folded weights
    float* qs   = wsm + 64 * WROW;                    // [128]

    const int t  = threadIdx.x;
    const int w  = t >> 5;        // softmax: side (warp-uniform)
    const int pL = t & 31;        // softmax: position
    const int c  = t & 3;         // MLP: j-chunk
    const int p  = t >> 2;        // MLP: position
    const int blockStart = blockIdx.x * TPB;
    const float b2v = __ldg(b2);
    const float NI  = __int_as_float(0xff800000);   // -inf

    const uint32_t buf0u = (uint32_t)__cvta_generic_to_shared(buf0);
    const uint32_t buf1u = (uint32_t)__cvta_generic_to_shared(buf1);
    const float4* g4 = (const float4*)(pred + (size_t)blockStart * DPOS);

    // ---- prologue: start tile 0 copy into buf0 (overlaps weight build) ----
    {
        #pragma unroll
        for (int j = 0; j < 8; j++)
            cp16(buf0u + (uint32_t)(t + j * TPB) * 16u, g4 + t + j * TPB);
        if (t < 32)
            cp16(buf0u + (uint32_t)(t + 8 * TPB) * 16u, g4 + t + 8 * TPB);
        CP_COMMIT();
    }

    // ---- folded weight table: wsm[j][k] ----
    // k<16: w_eff[j][4s+i] = w1[j][5s+i] + 0.25*w1[j][5s+4]; k16=b1[j]; k17=w2[j]
    #pragma unroll
    for (int k = 0; k < (64 * WROW) / TPB; k++) {
        int f   = t + k * TPB;
        int row = f / WROW;
        int cc  = f - row * WROW;
        float v = 0.f;
        if (cc < 16) {
            int ss = cc >> 2, ii = cc & 3;
            v = __ldg(w1 + row * 20 + 5 * ss + ii)
              + 0.25f * __ldg(w1 + row * 20 + 5 * ss + 4);
        } else if (cc == 16) v = __ldg(b1 + row);
        else if (cc == 17)   v = __ldg(w2 + row);
        wsm[f] = v;
    }

    const float4* sc4 = (const float4*)scores + (size_t)blockStart * (NCOUT / 4);
    float4*       ou4 = (float4*)out          + (size_t)blockStart * (NCOUT / 4);
    const int posA = t / (NCOUT / 4);
    const int remA = t - posA * (NCOUT / 4);
    // window offset within a buffer: row floats [B, B+33), B = pL*132 + 33w
    const int winOff = pL * DPOS + NBINS * w - w;     // f4-aligned (B mod 4 == w)

    #pragma unroll
    for (int tau = 0; tau < NTILES; tau++) {
        CP_WAIT0();
        __syncthreads();                       // buf(tau) visible to all

        float* bufC = (tau & 1) ? buf1 : buf0;

        // ---- issue copy(tau+1) NOW into the other buffer (full-tile window) ----
        if (tau < NTILES - 1) {
            uint32_t dstu = (tau & 1) ? buf0u : buf1u;
            const float4* gt = g4 + (tau + 1) * (TILE_POS * NBINS);
            #pragma unroll
            for (int j = 0; j < 8; j++)
                cp16(dstu + (uint32_t)(t + j * TPB) * 16u, gt + t + j * TPB);
            if (t < 32)
                cp16(dstu + (uint32_t)(t + 8 * TPB) * 16u, gt + t + 8 * TPB);
            CP_COMMIT();
        }

        // ---- prefetch this tile's scores (consumed at tile end) ----
        float4 rs0 = sc4[tau * 640 + t];
        float4 rs1 = sc4[tau * 640 + t + 128];
        float4 rs2 = sc4[tau * 640 + t + 256];
        float4 rs3 = sc4[tau * 640 + t + 384];
        float4 rs4 = sc4[tau * 640 + t + 512];

        // ---- softmax denom + top4: 9 aligned f4 + uniform mask + sort nets ----
        {
            const float4* win = (const float4*)(bufC + winOff);
            float r0, r1, r2, r3;
            float sum0, sum1;
            {
                float4 q0 = win[0];            // head: first w floats invalid
                if (w > 0) q0.x = NI;
                if (w > 1) q0.y = NI;
                if (w > 2) q0.z = NI;
                float e0 = ex2f(q0.x * LOG2E);
                float e1 = ex2f(q0.y * LOG2E);
                float e2 = ex2f(q0.z * LOG2E);
                float e3 = ex2f(q0.w * LOG2E);
                sum0 = e0 + e2; sum1 = e1 + e3;
                sort4(e0, e1, e2, e3, r0, r1, r2, r3);
            }
            #pragma unroll
            for (int g = 1; g < 8; g++) {
                float4 v = win[g];
                float e0 = ex2f(v.x * LOG2E);
                float e1 = ex2f(v.y * LOG2E);
                float e2 = ex2f(v.z * LOG2E);
                float e3 = ex2f(v.w * LOG2E);
                sum0 += e0 + e2; sum1 += e1 + e3;
                float a0, a1, a2, a3;
                sort4(e0, e1, e2, e3, a0, a1, a2, a3);
                merge4(r0, r1, r2, r3, a0, a1, a2, a3);
            }
            {
                float4 q8 = win[8];            // tail: last (3-w) floats invalid
                if (w < 3) q8.w = NI;
                if (w < 2) q8.z = NI;
                if (w < 1) q8.y = NI;
                float e0 = ex2f(q8.x * LOG2E);
                float e1 = ex2f(q8.y * LOG2E);
                float e2 = ex2f(q8.z * LOG2E);
                float e3 = ex2f(q8.w * LOG2E);
                sum0 += e0 + e2; sum1 += e1 + e3;
                float a0, a1, a2, a3;
                sort4(e0, e1, e2, e3, a0, a1, a2, a3);
                merge4(r0, r1, r2, r3, a0, a1, a2, a3);
            }
            float inv = rcpf(sum0 + sum1);
            *(float4*)(stat + pL * STAT_ROW + 4 * w) =
                make_float4(r0 * inv, r1 * inv, r2 * inv, r3 * inv);
        }
        __syncthreads();                       // stat ready (cross-warp)

        // ---- per-tile MLP: quad per position, 16 units/thread ----
        {
            const ulonglong2* srow = (const ulonglong2*)(stat + p * STAT_ROW);
            ulonglong2 sA = srow[0];
            ulonglong2 sB = srow[1];
            ulonglong2 sC = srow[2];
            ulonglong2 sD = srow[3];
            float q = 0.f;
            #pragma unroll 4
            for (int i = 0; i < 16; i++) {
                int j = 4 * i + c;             // broadcast LDS across quads
                const ulonglong2* wrow = (const ulonglong2*)(wsm + j * WROW);
                ulonglong2 wa = wrow[0];
                ulonglong2 wb = wrow[1];
                ulonglong2 wc2 = wrow[2];
                ulonglong2 wd = wrow[3];
                float2 bw = *(const float2*)(wsm + j * WROW + 16);

                u64 accA = fma2(wa.x, sA.x, 0ull);
                u64 accB = fma2(wc2.x, sC.x, 0ull);
                accA = fma2(wa.y, sA.y, accA);
                accB = fma2(wc2.y, sC.y, accB);
                accA = fma2(wb.x, sB.x, accA);
                accB = fma2(wd.x, sD.x, accB);
                accA = fma2(wb.y, sB.y, accA);
                accB = fma2(wd.y, sD.y, accB);

                u64 accS = addf2(accA, accB);
                float d0, d1; unpack2(accS, d0, d1);
                float h = (d0 + d1) + bw.x;
                h = fmaxf(h, 0.f);
                q = fmaf(h, bw.y, q);
            }
            q += __shfl_xor_sync(0xffffffffu, q, 1);
            q += __shfl_xor_sync(0xffffffffu, q, 2);
            if (c == 0) qs[p] = q + b2v;
        }
        __syncthreads();                       // qs(tau) visible

        // ---- out-add for this tile (scores already in regs) ----
        {
            int pp = posA, r = remA;
            float4 v; float qv;
            qv = qs[pp]; v = rs0;
            v.x += qv; v.y += qv; v.z += qv; v.w += qv;
            ou4[tau * 640 + t] = v;
            r += 8; pp += 6; if (r >= 20) { r -= 20; pp += 1; }
            qv = qs[pp]; v = rs1;
            v.x += qv; v.y += qv; v.z += qv; v.w += qv;
            ou4[tau * 640 + t + 128] = v;
            r += 8; pp += 6; if (r >= 20) { r -= 20; pp += 1; }
            qv = qs[pp]; v = rs2;
            v.x += qv; v.y += qv; v.z += qv; v.w += qv;
            ou4[tau * 640 + t + 256] = v;
            r += 8; pp += 6; if (r >= 20) { r -= 20; pp += 1; }
            qv = qs[pp]; v = rs3;
            v.x += qv; v.y += qv; v.z += qv; v.w += qv;
            ou4[tau * 640 + t + 384] = v;
            r += 8; pp += 6; if (r >= 20) { r -= 20; pp += 1; }
            qv = qs[pp]; v = rs4;
            v.x += qv; v.y += qv; v.z += qv; v.w += qv;
            ou4[tau * 640 + t + 512] = v;
        }
        __syncthreads();                       // qs reuse next tile
    }
}

extern "C" void kernel_launch(void* const* d_in, const int* in_sizes, int n_in,
                              void* d_out, int out_size)
{
    const float* scores = (const float*)d_in[0];
    const float* pred   = (const float*)d_in[1];
    const float* w1     = (const float*)d_in[2];
    const float* b1     = (const float*)d_in[3];
    const float* w2     = (const float*)d_in[4];
    const float* b2     = (const float*)d_in[5];
    // d_in[6] = k_top (fixed 4, compile-time specialized)

    int npos = in_sizes[1] / DPOS;     // 320000
    int grid = npos / TPB;             // 2500 exact

    size_t smem = (size_t)(2 * BUF_FLOATS + TILE_POS * STAT_ROW + 64 * WROW + TPB)
                  * sizeof(float);
    cudaFuncSetAttribute(lqe_kernel, cudaFuncAttributeMaxDynamicSharedMemorySize,
                         (int)smem);
    lqe_kernel<<<grid, TPB, smem>>>(scores, pred, w1, b1, w2, b2, (float*)d_out);
}

// round 12
// speedup vs baseline: 1.2880x; 1.0769x over previous
#include <cuda_runtime.h>
#include <cstdint>

// LQE_17841294147886 — fused softmax/top4/MLP/broadcast-add
// R11: MLP remap — each thread computes 8 hidden rows x 2 positions
//      (weights amortized 2x, rows j=rg+8i stride-80B conflict-free),
//      qs parity buffers drop the tile-end barrier (3 barriers/tile).
//      Double-buffered cp.async pipeline and softmax unchanged (82.4us base).

#define TPB        128
#define NBINS      33
#define DPOS       132
#define TILE_POS   32
#define NTILES     4
#define BUF_FLOATS (TILE_POS * DPOS)      // 4224 per buffer
#define STAT_ROW   20
#define WROW       20
#define NCOUT      80
#define LOG2E      1.4426950408889634f

typedef unsigned long long u64;

__device__ __forceinline__ u64 fma2(u64 a, u64 b, u64 c) {
    u64 d; asm("fma.rn.f32x2 %0, %1, %2, %3;" : "=l"(d) : "l"(a), "l"(b), "l"(c));
    return d;
}
__device__ __forceinline__ u64 addf2(u64 a, u64 b) {
    u64 d; asm("add.rn.f32x2 %0, %1, %2;" : "=l"(d) : "l"(a), "l"(b));
    return d;
}
__device__ __forceinline__ void unpack2(u64 v, float& lo, float& hi) {
    asm("mov.b64 {%0, %1}, %2;" : "=f"(lo), "=f"(hi) : "l"(v));
}
__device__ __forceinline__ float ex2f(float x) {
    float r; asm("ex2.approx.f32 %0, %1;" : "=f"(r) : "f"(x));
    return r;
}
__device__ __forceinline__ float rcpf(float x) {
    float r; asm("rcp.approx.f32 %0, %1;" : "=f"(r) : "f"(x));
    return r;
}
__device__ __forceinline__ void cp16(uint32_t dst, const void* src) {
    asm volatile("cp.async.cg.shared.global [%0], [%1], 16;"
                 :: "r"(dst), "l"(src));
}
#define CP_COMMIT() asm volatile("cp.async.commit_group;" ::: "memory")
#define CP_WAIT0()  asm volatile("cp.async.wait_group 0;" ::: "memory")

// sort 4 floats descending: 10 ops
__device__ __forceinline__ void sort4(float x0, float x1, float x2, float x3,
                                      float& a, float& b, float& c, float& d) {
    float p = fmaxf(x0, x1), q = fminf(x0, x1);
    float r = fmaxf(x2, x3), s = fminf(x2, x3);
    a = fmaxf(p, r); float tt = fminf(p, r);
    d = fminf(q, s); float u  = fmaxf(q, s);
    b = fmaxf(tt, u); c = fminf(tt, u);
}
// merge sorted-desc R with sorted-desc A -> top4 desc in R: 12 ops
__device__ __forceinline__ void merge4(float& r0, float& r1, float& r2, float& r3,
                                       float a0, float a1, float a2, float a3) {
    float L0 = fmaxf(r0, a3), L1 = fmaxf(r1, a2);
    float L2 = fmaxf(r2, a1), L3 = fmaxf(r3, a0);
    float m0 = fmaxf(L0, L2), m2 = fminf(L0, L2);
    float m1 = fmaxf(L1, L3), m3 = fminf(L1, L3);
    r0 = fmaxf(m0, m1); r1 = fminf(m0, m1);
    r2 = fmaxf(m2, m3); r3 = fminf(m2, m3);
}

__global__ __launch_bounds__(TPB, 5)
void lqe_kernel(const float* __restrict__ scores,
                const float* __restrict__ pred,
                const float* __restrict__ w1,
                const float* __restrict__ b1,
                const float* __restrict__ w2,
                const float* __restrict__ b2,
                float* __restrict__ out)
{
    extern __shared__ float smem[];
    float* buf0 = smem;                               // [32][132] tile buffer A
    float* buf1 = smem + BUF_FLOATS;                  // [32][132] tile buffer B
    float* stat = smem + 2 * BUF_FLOATS;              // [32][20] packed stats
    float* wsm  = stat + TILE_POS * STAT_ROW;         // [64][20] folded weights
    float* qs   = wsm + 64 * WROW;                    // [2][32] parity q buffers

    const int t  = threadIdx.x;
    const int w  = t >> 5;        // softmax: side (warp-uniform)
    const int pL = t & 31;        // softmax: position
    const int pg = t >> 3;        // MLP: position group (0..15)
    const int rg = t & 7;         // MLP: row group (0..7)
    const int blockStart = blockIdx.x * TPB;
    const float b2v = __ldg(b2);
    const float NI  = __int_as_float(0xff800000);   // -inf

    const uint32_t buf0u = (uint32_t)__cvta_generic_to_shared(buf0);
    const uint32_t buf1u = (uint32_t)__cvta_generic_to_shared(buf1);
    const float4* g4 = (const float4*)(pred + (size_t)blockStart * DPOS);

    // ---- prologue: start tile 0 copy into buf0 (overlaps weight build) ----
    {
        #pragma unroll
        for (int j = 0; j < 8; j++)
            cp16(buf0u + (uint32_t)(t + j * TPB) * 16u, g4 + t + j * TPB);
        if (t < 32)
            cp16(buf0u + (uint32_t)(t + 8 * TPB) * 16u, g4 + t + 8 * TPB);
        CP_COMMIT();
    }

    // ---- folded weight table: wsm[j][k] ----
    // k<16: w_eff[j][4s+i] = w1[j][5s+i] + 0.25*w1[j][5s+4]; k16=b1[j]; k17=w2[j]
    #pragma unroll
    for (int k = 0; k < (64 * WROW) / TPB; k++) {
        int f   = t + k * TPB;
        int row = f / WROW;
        int cc  = f - row * WROW;
        float v = 0.f;
        if (cc < 16) {
            int ss = cc >> 2, ii = cc & 3;
            v = __ldg(w1 + row * 20 + 5 * ss + ii)
              + 0.25f * __ldg(w1 + row * 20 + 5 * ss + 4);
        } else if (cc == 16) v = __ldg(b1 + row);
        else if (cc == 17)   v = __ldg(w2 + row);
        wsm[f] = v;
    }

    const float4* sc4 = (const float4*)scores + (size_t)blockStart * (NCOUT / 4);
    float4*       ou4 = (float4*)out          + (size_t)blockStart * (NCOUT / 4);
    const int posA = t / (NCOUT / 4);
    const int remA = t - posA * (NCOUT / 4);
    // window offset within a buffer: row floats [B, B+33), B = pL*132 + 33w
    const int winOff = pL * DPOS + NBINS * w - w;     // f4-aligned (B mod 4 == w)

    #pragma unroll
    for (int tau = 0; tau < NTILES; tau++) {
        CP_WAIT0();
        __syncthreads();                       // buf(tau) visible to all

        float* bufC = (tau & 1) ? buf1 : buf0;

        // ---- issue copy(tau+1) NOW into the other buffer (full-tile window) ----
        if (tau < NTILES - 1) {
            uint32_t dstu = (tau & 1) ? buf0u : buf1u;
            const float4* gt = g4 + (tau + 1) * (TILE_POS * NBINS);
            #pragma unroll
            for (int j = 0; j < 8; j++)
                cp16(dstu + (uint32_t)(t + j * TPB) * 16u, gt + t + j * TPB);
            if (t < 32)
                cp16(dstu + (uint32_t)(t + 8 * TPB) * 16u, gt + t + 8 * TPB);
            CP_COMMIT();
        }

        // ---- prefetch this tile's scores (consumed at tile end) ----
        float4 rs0 = sc4[tau * 640 + t];
        float4 rs1 = sc4[tau * 640 + t + 128];
        float4 rs2 = sc4[tau * 640 + t + 256];
        float4 rs3 = sc4[tau * 640 + t + 384];
        float4 rs4 = sc4[tau * 640 + t + 512];

        // ---- softmax denom + top4: 9 aligned f4 + uniform mask + sort nets ----
        {
            const float4* win = (const float4*)(bufC + winOff);
            float r0, r1, r2, r3;
            float sum0, sum1;
            {
                float4 q0 = win[0];            // head: first w floats invalid
                if (w > 0) q0.x = NI;
                if (w > 1) q0.y = NI;
                if (w > 2) q0.z = NI;
                float e0 = ex2f(q0.x * LOG2E);
                float e1 = ex2f(q0.y * LOG2E);
                float e2 = ex2f(q0.z * LOG2E);
                float e3 = ex2f(q0.w * LOG2E);
                sum0 = e0 + e2; sum1 = e1 + e3;
                sort4(e0, e1, e2, e3, r0, r1, r2, r3);
            }
            #pragma unroll
            for (int g = 1; g < 8; g++) {
                float4 v = win[g];
                float e0 = ex2f(v.x * LOG2E);
                float e1 = ex2f(v.y * LOG2E);
                float e2 = ex2f(v.z * LOG2E);
                float e3 = ex2f(v.w * LOG2E);
                sum0 += e0 + e2; sum1 += e1 + e3;
                float a0, a1, a2, a3;
                sort4(e0, e1, e2, e3, a0, a1, a2, a3);
                merge4(r0, r1, r2, r3, a0, a1, a2, a3);
            }
            {
                float4 q8 = win[8];            // tail: last (3-w) floats invalid
                if (w < 3) q8.w = NI;
                if (w < 2) q8.z = NI;
                if (w < 1) q8.y = NI;
                float e0 = ex2f(q8.x * LOG2E);
                float e1 = ex2f(q8.y * LOG2E);
                float e2 = ex2f(q8.z * LOG2E);
                float e3 = ex2f(q8.w * LOG2E);
                sum0 += e0 + e2; sum1 += e1 + e3;
                float a0, a1, a2, a3;
                sort4(e0, e1, e2, e3, a0, a1, a2, a3);
                merge4(r0, r1, r2, r3, a0, a1, a2, a3);
            }
            float inv = rcpf(sum0 + sum1);
            *(float4*)(stat + pL * STAT_ROW + 4 * w) =
                make_float4(r0 * inv, r1 * inv, r2 * inv, r3 * inv);
        }
        __syncthreads();                       // stat ready (cross-warp)

        // ---- MLP: 8 rows (j = rg + 8i) x 2 positions (pg, pg+16) ----
        {
            const ulonglong2* sAr = (const ulonglong2*)(stat + pg * STAT_ROW);
            const ulonglong2* sBr = (const ulonglong2*)(stat + (pg + 16) * STAT_ROW);
            ulonglong2 aA = sAr[0], aB = sAr[1], aC = sAr[2], aD = sAr[3];
            ulonglong2 bA = sBr[0], bB = sBr[1], bC = sBr[2], bD = sBr[3];
            float qA = 0.f, qB = 0.f;
            #pragma unroll
            for (int i = 0; i < 8; i++) {
                int j = rg + 8 * i;            // stride-80B rows: conflict-free
                const ulonglong2* wrow = (const ulonglong2*)(wsm + j * WROW);
                ulonglong2 wa = wrow[0];
                ulonglong2 wb = wrow[1];
                ulonglong2 wc2 = wrow[2];
                ulonglong2 wd = wrow[3];
                float2 bw = *(const float2*)(wsm + j * WROW + 16);

                u64 xA = fma2(wa.x, aA.x, 0ull);
                u64 yA = fma2(wc2.x, aC.x, 0ull);
                u64 xB = fma2(wa.x, bA.x, 0ull);
                u64 yB = fma2(wc2.x, bC.x, 0ull);
                xA = fma2(wa.y, aA.y, xA);  yA = fma2(wc2.y, aC.y, yA);
                xB = fma2(wa.y, bA.y, xB);  yB = fma2(wc2.y, bC.y, yB);
                xA = fma2(wb.x, aB.x, xA);  yA = fma2(wd.x, aD.x, yA);
                xB = fma2(wb.x, bB.x, xB);  yB = fma2(wd.x, bD.x, yB);
                xA = fma2(wb.y, aB.y, xA);  yA = fma2(wd.y, aD.y, yA);
                xB = fma2(wb.y, bB.y, xB);  yB = fma2(wd.y, bD.y, yB);

                u64 sA2 = addf2(xA, yA);
                u64 sB2 = addf2(xB, yB);
                float a0, a1, c0, c1;
                unpack2(sA2, a0, a1);
                unpack2(sB2, c0, c1);
                float hA = (a0 + a1) + bw.x;
                float hB = (c0 + c1) + bw.x;
                hA = fmaxf(hA, 0.f);
                hB = fmaxf(hB, 0.f);
                qA = fmaf(hA, bw.y, qA);
                qB = fmaf(hB, bw.y, qB);
            }
            qA += __shfl_xor_sync(0xffffffffu, qA, 1);
            qB += __shfl_xor_sync(0xffffffffu, qB, 1);
            qA += __shfl_xor_sync(0xffffffffu, qA, 2);
            qB += __shfl_xor_sync(0xffffffffu, qB, 2);
            qA += __shfl_xor_sync(0xffffffffu, qA, 4);
            qB += __shfl_xor_sync(0xffffffffu, qB, 4);
            if (rg == 0) {
                float* qb = qs + (tau & 1) * TILE_POS;
                qb[pg]      = qA + b2v;
                qb[pg + 16] = qB + b2v;
            }
        }
        __syncthreads();                       // qs(tau) visible

        // ---- out-add for this tile (scores already in regs) ----
        {
            const float* qb = qs + (tau & 1) * TILE_POS;
            int pp = posA, r = remA;
            float4 v; float qv;
            qv = qb[pp]; v = rs0;
            v.x += qv; v.y += qv; v.z += qv; v.w += qv;
            ou4[tau * 640 + t] = v;
            r += 8; pp += 6; if (r >= 20) { r -= 20; pp += 1; }
            qv = qb[pp]; v = rs1;
            v.x += qv; v.y += qv; v.z += qv; v.w += qv;
            ou4[tau * 640 + t + 128] = v;
            r += 8; pp += 6; if (r >= 20) { r -= 20; pp += 1; }
            qv = qb[pp]; v = rs2;
            v.x += qv; v.y += qv; v.z += qv; v.w += qv;
            ou4[tau * 640 + t + 256] = v;
            r += 8; pp += 6; if (r >= 20) { r -= 20; pp += 1; }
            qv = qb[pp]; v = rs3;
            v.x += qv; v.y += qv; v.z += qv; v.w += qv;
            ou4[tau * 640 + t + 384] = v;
            r += 8; pp += 6; if (r >= 20) { r -= 20; pp += 1; }
            qv = qb[pp]; v = rs4;
            v.x += qv; v.y += qv; v.z += qv; v.w += qv;
            ou4[tau * 640 + t + 512] = v;
        }
        // no tile-end barrier: next tile's qs write targets the other parity
        // buffer, and stat/buf hazards are covered by the tile-top barrier.
    }
}

extern "C" void kernel_launch(void* const* d_in, const int* in_sizes, int n_in,
                              void* d_out, int out_size)
{
    const float* scores = (const float*)d_in[0];
    const float* pred   = (const float*)d_in[1];
    const float* w1     = (const float*)d_in[2];
    const float* b1     = (const float*)d_in[3];
    const float* w2     = (const float*)d_in[4];
    const float* b2     = (const float*)d_in[5];
    // d_in[6] = k_top (fixed 4, compile-time specialized)

    int npos = in_sizes[1] / DPOS;     // 320000
    int grid = npos / TPB;             // 2500 exact

    size_t smem = (size_t)(2 * BUF_FLOATS + TILE_POS * STAT_ROW + 64 * WROW
                           + 2 * TILE_POS) * sizeof(float);
    cudaFuncSetAttribute(lqe_kernel, cudaFuncAttributeMaxDynamicSharedMemorySize,
                         (int)smem);
    lqe_kernel<<<grid, TPB, smem>>>(scores, pred, w1, b1, w2, b2, (float*)d_out);
}

// round 13
// speedup vs baseline: 1.2978x; 1.0076x over previous
#include <cuda_runtime.h>
#include <cstdint>

// LQE_17841294147886 — fused softmax/top4/MLP/broadcast-add
// R12: fully warp-local tiles. Quad softmax (scalar CF LDS, no masks),
//      in-warp MLP (2pos x 8rows), per-warp out chunks -> ONE barrier/tile
//      (was 3). Double-buffered cp.async pipeline unchanged (76.5us base).

#define TPB        128
#define NBINS      33
#define DPOS       132
#define TILE_POS   32
#define NTILES     4
#define BUF_FLOATS (TILE_POS * DPOS)      // 4224 per buffer
#define STAT_ROW   20
#define WROW       20
#define NCOUT      80
#define LOG2E      1.4426950408889634f

typedef unsigned long long u64;

__device__ __forceinline__ u64 fma2(u64 a, u64 b, u64 c) {
    u64 d; asm("fma.rn.f32x2 %0, %1, %2, %3;" : "=l"(d) : "l"(a), "l"(b), "l"(c));
    return d;
}
__device__ __forceinline__ u64 addf2(u64 a, u64 b) {
    u64 d; asm("add.rn.f32x2 %0, %1, %2;" : "=l"(d) : "l"(a), "l"(b));
    return d;
}
__device__ __forceinline__ void unpack2(u64 v, float& lo, float& hi) {
    asm("mov.b64 {%0, %1}, %2;" : "=f"(lo), "=f"(hi) : "l"(v));
}
__device__ __forceinline__ float ex2f(float x) {
    float r; asm("ex2.approx.f32 %0, %1;" : "=f"(r) : "f"(x));
    return r;
}
__device__ __forceinline__ float rcpf(float x) {
    float r; asm("rcp.approx.f32 %0, %1;" : "=f"(r) : "f"(x));
    return r;
}
__device__ __forceinline__ void cp16(uint32_t dst, const void* src) {
    asm volatile("cp.async.cg.shared.global [%0], [%1], 16;"
                 :: "r"(dst), "l"(src));
}
#define CP_COMMIT() asm volatile("cp.async.commit_group;" ::: "memory")
#define CP_WAIT0()  asm volatile("cp.async.wait_group 0;" ::: "memory")

// sort 4 floats descending: 10 ops
__device__ __forceinline__ void sort4(float x0, float x1, float x2, float x3,
                                      float& a, float& b, float& c, float& d) {
    float p = fmaxf(x0, x1), q = fminf(x0, x1);
    float r = fmaxf(x2, x3), s = fminf(x2, x3);
    a = fmaxf(p, r); float tt = fminf(p, r);
    d = fminf(q, s); float u  = fmaxf(q, s);
    b = fmaxf(tt, u); c = fminf(tt, u);
}
// merge sorted-desc R with sorted-desc A -> top4 desc in R: 12 ops
__device__ __forceinline__ void merge4(float& r0, float& r1, float& r2, float& r3,
                                       float a0, float a1, float a2, float a3) {
    float L0 = fmaxf(r0, a3), L1 = fmaxf(r1, a2);
    float L2 = fmaxf(r2, a1), L3 = fmaxf(r3, a0);
    float m0 = fmaxf(L0, L2), m2 = fminf(L0, L2);
    float m1 = fmaxf(L1, L3), m3 = fminf(L1, L3);
    r0 = fmaxf(m0, m1); r1 = fminf(m0, m1);
    r2 = fmaxf(m2, m3); r3 = fminf(m2, m3);
}
// insert e into sorted-desc top4: 7 ops
__device__ __forceinline__ void top4_push(float e, float& t0, float& t1,
                                          float& t2, float& t3) {
    float c0 = fminf(t0, e);  t0 = fmaxf(t0, e);
    float c1 = fminf(t1, c0); t1 = fmaxf(t1, c0);
    float c2 = fminf(t2, c1); t2 = fmaxf(t2, c1);
    t3 = fmaxf(t3, c2);
}

__global__ __launch_bounds__(TPB, 5)
void lqe_kernel(const float* __restrict__ scores,
                const float* __restrict__ pred,
                const float* __restrict__ w1,
                const float* __restrict__ b1,
                const float* __restrict__ w2,
                const float* __restrict__ b2,
                float* __restrict__ out)
{
    extern __shared__ float smem[];
    float* buf0 = smem;                               // [32][132] tile buffer A
    float* buf1 = smem + BUF_FLOATS;                  // [32][132] tile buffer B
    float* stat = smem + 2 * BUF_FLOATS;              // [32][20] packed stats
    float* wsm  = stat + TILE_POS * STAT_ROW;         // [64][20] folded weights
    float* qs   = wsm + 64 * WROW;                    // [32] per-warp q slots

    const int t  = threadIdx.x;
    const int l  = t & 31;        // lane
    const int w  = t >> 5;        // warp: owns positions w*8 .. w*8+7
    const int sm_pos = l >> 2;    // softmax: local pos in warp (0..7)
    const int sm_sid = l & 3;     // softmax: side
    const int pg = l >> 3;        // MLP: position subgroup (0..3)
    const int rg = l & 7;         // MLP: row group (0..7)
    const int blockStart = blockIdx.x * TPB;
    const float b2v = __ldg(b2);

    const uint32_t buf0u = (uint32_t)__cvta_generic_to_shared(buf0);
    const uint32_t buf1u = (uint32_t)__cvta_generic_to_shared(buf1);
    const float4* g4 = (const float4*)(pred + (size_t)blockStart * DPOS);

    // ---- prologue: start tile 0 copy into buf0 (overlaps weight build) ----
    {
        #pragma unroll
        for (int j = 0; j < 8; j++)
            cp16(buf0u + (uint32_t)(t + j * TPB) * 16u, g4 + t + j * TPB);
        if (t < 32)
            cp16(buf0u + (uint32_t)(t + 8 * TPB) * 16u, g4 + t + 8 * TPB);
        CP_COMMIT();
    }

    // ---- folded weight table: wsm[j][k] ----
    // k<16: w_eff[j][4s+i] = w1[j][5s+i] + 0.25*w1[j][5s+4]; k16=b1[j]; k17=w2[j]
    #pragma unroll
    for (int k = 0; k < (64 * WROW) / TPB; k++) {
        int f   = t + k * TPB;
        int row = f / WROW;
        int cc  = f - row * WROW;
        float v = 0.f;
        if (cc < 16) {
            int ss = cc >> 2, ii = cc & 3;
            v = __ldg(w1 + row * 20 + 5 * ss + ii)
              + 0.25f * __ldg(w1 + row * 20 + 5 * ss + 4);
        } else if (cc == 16) v = __ldg(b1 + row);
        else if (cc == 17)   v = __ldg(w2 + row);
        wsm[f] = v;
    }

    const float4* sc4 = (const float4*)scores + (size_t)blockStart * (NCOUT / 4);
    float4*       ou4 = (float4*)out          + (size_t)blockStart * (NCOUT / 4);
    // softmax row offset inside buffer (scalar reads, CF banks 4*pos+sid+k)
    const int rowOff = (w * 8 + sm_pos) * DPOS + sm_sid * NBINS;
    // out-phase base: warp chunk is 160 f4; lane starts at p0 = l/20
    const int p0 = l / 20;
    const int r0 = l - p0 * 20;

    #pragma unroll
    for (int tau = 0; tau < NTILES; tau++) {
        CP_WAIT0();
        __syncthreads();                       // buf(tau) visible; ONLY barrier

        float* bufC = (tau & 1) ? buf1 : buf0;

        // ---- issue copy(tau+1) NOW into the other buffer (full-tile window) ----
        if (tau < NTILES - 1) {
            uint32_t dstu = (tau & 1) ? buf0u : buf1u;
            const float4* gt = g4 + (tau + 1) * (TILE_POS * NBINS);
            #pragma unroll
            for (int j = 0; j < 8; j++)
                cp16(dstu + (uint32_t)(t + j * TPB) * 16u, gt + t + j * TPB);
            if (t < 32)
                cp16(dstu + (uint32_t)(t + 8 * TPB) * 16u, gt + t + 8 * TPB);
            CP_COMMIT();
        }

        // ---- prefetch this tile's scores for the warp's own chunk ----
        const int cBase = tau * 640 + w * 160;
        float4 rs0 = sc4[cBase + l];
        float4 rs1 = sc4[cBase + l + 32];
        float4 rs2 = sc4[cBase + l + 64];
        float4 rs3 = sc4[cBase + l + 96];
        float4 rs4 = sc4[cBase + l + 128];

        // ---- softmax + top4: quad mapping, 33 scalar CF LDS, no masks ----
        {
            const float* x = bufC + rowOff;
            float r0s, r1s, r2s, r3s;
            float sum0, sum1;
            {
                float e0 = ex2f(x[0] * LOG2E);
                float e1 = ex2f(x[1] * LOG2E);
                float e2 = ex2f(x[2] * LOG2E);
                float e3 = ex2f(x[3] * LOG2E);
                sum0 = e0 + e2; sum1 = e1 + e3;
                sort4(e0, e1, e2, e3, r0s, r1s, r2s, r3s);
            }
            #pragma unroll
            for (int g = 1; g < 8; g++) {
                float e0 = ex2f(x[4 * g + 0] * LOG2E);
                float e1 = ex2f(x[4 * g + 1] * LOG2E);
                float e2 = ex2f(x[4 * g + 2] * LOG2E);
                float e3 = ex2f(x[4 * g + 3] * LOG2E);
                sum0 += e0 + e2; sum1 += e1 + e3;
                float a0, a1, a2, a3;
                sort4(e0, e1, e2, e3, a0, a1, a2, a3);
                merge4(r0s, r1s, r2s, r3s, a0, a1, a2, a3);
            }
            {
                float e = ex2f(x[32] * LOG2E);
                sum0 += e;
                top4_push(e, r0s, r1s, r2s, r3s);
            }
            float inv = rcpf(sum0 + sum1);
            *(float4*)(stat + (w * 8 + sm_pos) * STAT_ROW + 4 * sm_sid) =
                make_float4(r0s * inv, r1s * inv, r2s * inv, r3s * inv);
        }
        __syncwarp();                          // stat is warp-local now

        // ---- MLP: 8 rows (j = rg + 8i) x 2 positions (w8+pg, w8+pg+4) ----
        {
            const ulonglong2* sAr =
                (const ulonglong2*)(stat + (w * 8 + pg) * STAT_ROW);
            const ulonglong2* sBr =
                (const ulonglong2*)(stat + (w * 8 + pg + 4) * STAT_ROW);
            ulonglong2 aA = sAr[0], aB = sAr[1], aC = sAr[2], aD = sAr[3];
            ulonglong2 bA = sBr[0], bB = sBr[1], bC = sBr[2], bD = sBr[3];
            float qA = 0.f, qB = 0.f;
            #pragma unroll
            for (int i = 0; i < 8; i++) {
                int j = rg + 8 * i;            // stride-80B rows: conflict-free
                const ulonglong2* wrow = (const ulonglong2*)(wsm + j * WROW);
                ulonglong2 wa = wrow[0];
                ulonglong2 wb = wrow[1];
                ulonglong2 wc2 = wrow[2];
                ulonglong2 wd = wrow[3];
                float2 bw = *(const float2*)(wsm + j * WROW + 16);

                u64 xA = fma2(wa.x, aA.x, 0ull);
                u64 yA = fma2(wc2.x, aC.x, 0ull);
                u64 xB = fma2(wa.x, bA.x, 0ull);
                u64 yB = fma2(wc2.x, bC.x, 0ull);
                xA = fma2(wa.y, aA.y, xA);  yA = fma2(wc2.y, aC.y, yA);
                xB = fma2(wa.y, bA.y, xB);  yB = fma2(wc2.y, bC.y, yB);
                xA = fma2(wb.x, aB.x, xA);  yA = fma2(wd.x, aD.x, yA);
                xB = fma2(wb.x, bB.x, xB);  yB = fma2(wd.x, bD.x, yB);
                xA = fma2(wb.y, aB.y, xA);  yA = fma2(wd.y, aD.y, yA);
                xB = fma2(wb.y, bB.y, xB);  yB = fma2(wd.y, bD.y, yB);

                u64 sA2 = addf2(xA, yA);
                u64 sB2 = addf2(xB, yB);
                float a0, a1, c0, c1;
                unpack2(sA2, a0, a1);
                unpack2(sB2, c0, c1);
                float hA = (a0 + a1) + bw.x;
                float hB = (c0 + c1) + bw.x;
                hA = fmaxf(hA, 0.f);
                hB = fmaxf(hB, 0.f);
                qA = fmaf(hA, bw.y, qA);
                qB = fmaf(hB, bw.y, qB);
            }
            qA += __shfl_xor_sync(0xffffffffu, qA, 1);
            qB += __shfl_xor_sync(0xffffffffu, qB, 1);
            qA += __shfl_xor_sync(0xffffffffu, qA, 2);
            qB += __shfl_xor_sync(0xffffffffu, qB, 2);
            qA += __shfl_xor_sync(0xffffffffu, qA, 4);
            qB += __shfl_xor_sync(0xffffffffu, qB, 4);
            if (rg == 0) {
                qs[w * 8 + pg]     = qA + b2v;
                qs[w * 8 + pg + 4] = qB + b2v;
            }
        }
        __syncwarp();                          // qs warp-local

        // ---- out-add: warp's contiguous 160-f4 chunk, coalesced ----
        {
            const float* qb = qs + w * 8;
            int pp = p0, r = r0;
            float4 v; float qv;
            qv = qb[pp]; v = rs0;
            v.x += qv; v.y += qv; v.z += qv; v.w += qv;
            ou4[cBase + l] = v;
            r += 12; pp += 1; if (r >= 20) { r -= 20; pp += 1; }
            qv = qb[pp]; v = rs1;
            v.x += qv; v.y += qv; v.z += qv; v.w += qv;
            ou4[cBase + l + 32] = v;
            r += 12; pp += 1; if (r >= 20) { r -= 20; pp += 1; }
            qv = qb[pp]; v = rs2;
            v.x += qv; v.y += qv; v.z += qv; v.w += qv;
            ou4[cBase + l + 64] = v;
            r += 12; pp += 1; if (r >= 20) { r -= 20; pp += 1; }
            qv = qb[pp]; v = rs3;
            v.x += qv; v.y += qv; v.z += qv; v.w += qv;
            ou4[cBase + l + 96] = v;
            r += 12; pp += 1; if (r >= 20) { r -= 20; pp += 1; }
            qv = qb[pp]; v = rs4;
            v.x += qv; v.y += qv; v.z += qv; v.w += qv;
            ou4[cBase + l + 128] = v;
        }
        // no further barriers: all per-tile state (stat, qs) is warp-private;
        // buf hazard is covered by the next tile's top barrier.
    }
}

extern "C" void kernel_launch(void* const* d_in, const int* in_sizes, int n_in,
                              void* d_out, int out_size)
{
    const float* scores = (const float*)d_in[0];
    const float* pred   = (const float*)d_in[1];
    const float* w1     = (const float*)d_in[2];
    const float* b1     = (const float*)d_in[3];
    const float* w2     = (const float*)d_in[4];
    const float* b2     = (const float*)d_in[5];
    // d_in[6] = k_top (fixed 4, compile-time specialized)

    int npos = in_sizes[1] / DPOS;     // 320000
    int grid = npos / TPB;             // 2500 exact

    size_t smem = (size_t)(2 * BUF_FLOATS + TILE_POS * STAT_ROW + 64 * WROW
                           + TILE_POS) * sizeof(float);
    cudaFuncSetAttribute(lqe_kernel, cudaFuncAttributeMaxDynamicSharedMemorySize,
                         (int)smem);
    lqe_kernel<<<grid, TPB, smem>>>(scores, pred, w1, b1, w2, b2, (float*)d_out);
}